// round 8
// baseline (speedup 1.0000x reference)
#include <cuda_runtime.h>
#include <math.h>

#define BB   4
#define CH   32
#define GCH  384
#define HH   224
#define WW   224
#define HW   50176
#define NPLANE 6422528        // 4*32*224*224
#define N4     1605632        // NPLANE/4
#define WT   4                // scan steps per tile
#define NTB  56               // 224/4
#define ESTR 226              // element stride for nrm/hb (224 + pad)
#define OSTR 233              // to-buffer stride

// Scratch (static device globals)
__device__ __align__(16) float g_y32[NPLANE];        // conv1 output
__device__ __align__(16) float g_dirA[4 * NPLANE];   // pass-1 directional outputs
__device__ __align__(16) float g_dirB[4 * NPLANE];   // pass-2 directional outputs
__device__ __align__(16) float g_s1[NPLANE];         // max of pass-1

// ---------------------------------------------------------------------------
// conv1: y [4,2,224,224] -> g_y32 [4,32,224,224], 3x3 same
// ---------------------------------------------------------------------------
__global__ void __launch_bounds__(224) conv1_kernel(
    const float* __restrict__ y, const float* __restrict__ w3)
{
    int b = blockIdx.x / HH;
    int h = blockIdx.x % HH;
    int tid = threadIdx.x;

    __shared__ float si[2][3][WW + 2];
    __shared__ float sw[32 * 2 * 9];

    for (int i = tid; i < 576; i += 224) sw[i] = w3[i];

    #pragma unroll
    for (int ic = 0; ic < 2; ic++)
        #pragma unroll
        for (int r = 0; r < 3; r++) {
            int hh = h + r - 1;
            float v = (hh >= 0 && hh < HH)
                        ? y[((size_t)(b * 2 + ic) * HH + hh) * WW + tid] : 0.f;
            si[ic][r][tid + 1] = v;
            if (tid < 2) si[ic][r][tid * (WW + 1)] = 0.f;
        }
    __syncthreads();

    float v[18];
    #pragma unroll
    for (int ic = 0; ic < 2; ic++)
        #pragma unroll
        for (int r = 0; r < 3; r++)
            #pragma unroll
            for (int dx = 0; dx < 3; dx++)
                v[ic * 9 + r * 3 + dx] = si[ic][r][tid + dx];

    for (int oc = 0; oc < 32; oc++) {
        float acc = 0.f;
        #pragma unroll
        for (int k = 0; k < 18; k++) acc = fmaf(v[k], sw[oc * 18 + k], acc);
        g_y32[((size_t)(b * 32 + oc) * HH + h) * WW + tid] = acc;
    }
}

// ---------------------------------------------------------------------------
// Propagation: 2 planes per CTA (c, c+16), gates normalized at load time.
// Scan step: 1 LDS.128 + 2 hb LDS + 3 FMA + STS, one barrier per step
// shared by both planes. dir map: 0=lr(hor,fwd) 1=rl(vert,rev)
// 2=du(vert,fwd) 3=ud(hor,rev)
// ---------------------------------------------------------------------------
__global__ void __launch_bounds__(224) prop_kernel(
    const float* __restrict__ gates, int pass)
{
    int pid = blockIdx.x;           // 0..255
    int d  = pid >> 6;
    int r  = pid & 63;
    int b  = r >> 4;
    int c0 = r & 15;                // planes c0 and c0+16
    bool hor = (d == 0 || d == 3);
    bool rev = (d == 1 || d == 3);

    const float* xin  = pass ? g_s1 : g_y32;
    float*       dirO = pass ? g_dirB : g_dirA;

    const float* xp[2]; float* op[2];
    const float* g1p[2]; const float* g2p[2]; const float* g3p[2];
    #pragma unroll
    for (int k = 0; k < 2; k++) {
        int c  = c0 + 16 * k;
        int bc = b * 32 + c;
        xp[k]  = xin + (size_t)bc * HW;
        op[k]  = dirO + (size_t)(d * 128 + bc) * HW;
        g1p[k] = gates + ((size_t)b * GCH + d * 96 + c) * HW;
        g2p[k] = g1p[k] + (size_t)32 * HW;
        g3p[k] = g1p[k] + (size_t)64 * HW;
    }

    __shared__ float4 nrm[2][WT][ESTR];     // normalized (s1,s2,s3,base)
    __shared__ float  to[2][WT][OSTR];      // output staging (hor only)
    __shared__ float  hb[2][2][ESTR];       // h line, [plane][parity][e+1]

    int tid = threadIdx.x;
    for (int i = tid; i < 2 * 2 * ESTR; i += 224) ((float*)hb)[i] = 0.f;
    __syncthreads();

    float hreg0 = 0.f, hreg1 = 0.f;

    for (int tb = 0; tb < NTB; tb++) {
        int t0 = tb * WT;

        // ---- load + normalize (off the barrier-paced path) ----
        if (hor) {
            #pragma unroll
            for (int i = 0; i < WT; i++) {
                int idx = i * 224 + tid;     // 0..895
                int s = idx >> 2, j = idx & 3;
                int tg = rev ? (223 - t0 - j) : (t0 + j);
                int off = s * WW + tg;
                #pragma unroll
                for (int k = 0; k < 2; k++) {
                    float a1 = g1p[k][off], a2 = g2p[k][off],
                          a3 = g3p[k][off], xv = xp[k][off];
                    float inv = __fdividef(1.0f,
                        fmaxf(fabsf(a1) + fabsf(a2) + fabsf(a3), 1.0f));
                    nrm[k][j][s] = make_float4(a1 * inv, a2 * inv, a3 * inv,
                        (1.0f - (a1 + a2 + a3) * inv) * xv);
                }
            }
        } else {
            #pragma unroll
            for (int i = 0; i < WT; i++) {
                int tg = rev ? (223 - t0 - i) : (t0 + i);
                int off = tg * WW + tid;
                #pragma unroll
                for (int k = 0; k < 2; k++) {
                    float a1 = g1p[k][off], a2 = g2p[k][off],
                          a3 = g3p[k][off], xv = xp[k][off];
                    float inv = __fdividef(1.0f,
                        fmaxf(fabsf(a1) + fabsf(a2) + fabsf(a3), 1.0f));
                    nrm[k][i][tid] = make_float4(a1 * inv, a2 * inv, a3 * inv,
                        (1.0f - (a1 + a2 + a3) * inv) * xv);
                }
            }
        }
        __syncthreads();

        // ---- serial scan over WT steps (lean, barrier-paced) ----
        #pragma unroll
        for (int j = 0; j < WT; j++) {
            int t = t0 + j;
            int par = t & 1;
            float4 q0 = nrm[0][j][tid];
            float4 q1 = nrm[1][j][tid];
            float hn0 = fmaf(q0.x, hb[0][par][tid],
                        fmaf(q0.y, hreg0,
                        fmaf(q0.z, hb[0][par][tid + 2], q0.w)));
            float hn1 = fmaf(q1.x, hb[1][par][tid],
                        fmaf(q1.y, hreg1,
                        fmaf(q1.z, hb[1][par][tid + 2], q1.w)));
            hb[0][par ^ 1][tid + 1] = hn0;
            hb[1][par ^ 1][tid + 1] = hn1;
            if (hor) {
                to[0][j][tid] = hn0;
                to[1][j][tid] = hn1;
            } else {
                int tg = rev ? (223 - t) : t;
                op[0][tg * WW + tid] = hn0;
                op[1][tg * WW + tid] = hn1;
            }
            hreg0 = hn0;
            hreg1 = hn1;
            __syncthreads();
        }

        // ---- flush (hor only; reads ordered vs rewrites by next step-barrier)
        if (hor) {
            #pragma unroll
            for (int i = 0; i < WT; i++) {
                int idx = i * 224 + tid;
                int s = idx >> 2, j = idx & 3;
                int tg = rev ? (223 - t0 - j) : (t0 + j);
                op[0][s * WW + tg] = to[0][j][s];
                op[1][s * WW + tg] = to[1][j][s];
            }
        }
    }
}

// ---------------------------------------------------------------------------
// max over 4 pass-1 direction buffers -> g_s1
// ---------------------------------------------------------------------------
__global__ void max_kernel()
{
    int i = blockIdx.x * blockDim.x + threadIdx.x;
    if (i >= N4) return;
    const float4* d0 = (const float4*)g_dirA;
    float4 a = d0[i];
    float4 b = d0[i + N4];
    float4 c = d0[i + 2 * N4];
    float4 e = d0[i + 3 * N4];
    float4 r;
    r.x = fmaxf(fmaxf(a.x, b.x), fmaxf(c.x, e.x));
    r.y = fmaxf(fmaxf(a.y, b.y), fmaxf(c.y, e.y));
    r.z = fmaxf(fmaxf(a.z, b.z), fmaxf(c.z, e.z));
    r.w = fmaxf(fmaxf(a.w, b.w), fmaxf(c.w, e.w));
    ((float4*)g_s1)[i] = r;
}

// ---------------------------------------------------------------------------
// conv2 (32->2, 3x3 same) fused with max over 4 pass-2 dirs + log_softmax
// ---------------------------------------------------------------------------
__global__ void __launch_bounds__(224) conv2_ls_kernel(
    const float* __restrict__ w4, float* __restrict__ out)
{
    int b = blockIdx.x / HH;
    int h = blockIdx.x % HH;
    int tid = threadIdx.x;

    __shared__ float si[16][3][WW + 2];
    __shared__ float sw[2 * 32 * 9];

    for (int i = tid; i < 576; i += 224) sw[i] = w4[i];

    float acc0 = 0.f, acc1 = 0.f;

    for (int chunk = 0; chunk < 2; chunk++) {
        __syncthreads();
        for (int icl = 0; icl < 16; icl++) {
            int ic = chunk * 16 + icl;
            #pragma unroll
            for (int r = 0; r < 3; r++) {
                int hh = h + r - 1;
                float v = 0.f;
                if (hh >= 0 && hh < HH) {
                    size_t base = ((size_t)(b * 32 + ic) * HH + hh) * WW + tid;
                    float v0 = g_dirB[base];
                    float v1 = g_dirB[base + 1 * (size_t)NPLANE];
                    float v2 = g_dirB[base + 2 * (size_t)NPLANE];
                    float v3 = g_dirB[base + 3 * (size_t)NPLANE];
                    v = fmaxf(fmaxf(v0, v1), fmaxf(v2, v3));
                }
                si[icl][r][tid + 1] = v;
                if (tid < 2) si[icl][r][tid * (WW + 1)] = 0.f;
            }
        }
        __syncthreads();
        for (int icl = 0; icl < 16; icl++) {
            int ic = chunk * 16 + icl;
            #pragma unroll
            for (int r = 0; r < 3; r++)
                #pragma unroll
                for (int dx = 0; dx < 3; dx++) {
                    float v = si[icl][r][tid + dx];
                    int k = ic * 9 + r * 3 + dx;
                    acc0 = fmaf(v, sw[k], acc0);
                    acc1 = fmaf(v, sw[288 + k], acc1);
                }
        }
    }

    float m  = fmaxf(acc0, acc1);
    float e0 = __expf(acc0 - m), e1 = __expf(acc1 - m);
    float lse = m + __logf(e0 + e1);
    size_t o = ((size_t)b * 2 * HH + h) * WW + tid;
    out[o]      = acc0 - lse;
    out[o + HW] = acc1 - lse;
}

// ---------------------------------------------------------------------------
extern "C" void kernel_launch(void* const* d_in, const int* in_sizes, int n_in,
                              void* d_out, int out_size)
{
    const float* gates = (const float*)d_in[0];  // [4,384,224,224]
    const float* y     = (const float*)d_in[1];  // [4,2,224,224]
    const float* w3    = (const float*)d_in[2];  // [32,2,3,3]
    const float* w4    = (const float*)d_in[3];  // [2,32,3,3]
    float* out = (float*)d_out;                  // [4,2,224,224]

    (void)in_sizes; (void)n_in; (void)out_size;

    conv1_kernel<<<BB * HH, 224>>>(y, w3);
    prop_kernel<<<256, 224>>>(gates, 0);     // -> g_dirA
    max_kernel<<<(N4 + 255) / 256, 256>>>(); // g_dirA -> g_s1
    prop_kernel<<<256, 224>>>(gates, 1);     // x=g_s1 -> g_dirB
    conv2_ls_kernel<<<BB * HH, 224>>>(w4, out);
}

// round 12
// speedup vs baseline: 1.7810x; 1.7810x over previous
#include <cuda_runtime.h>
#include <math.h>

#define BB   4
#define GCH  384
#define HH   224
#define WW   224
#define HW   50176
#define NPLANE 6422528        // 4*32*224*224
#define N4     1605632        // NPLANE/4
#define FULLMASK 0xffffffffu

// Scratch (static device globals)
__device__ __align__(16) float g_y32[NPLANE];
__device__ __align__(16) float g_dirA[4 * NPLANE];
__device__ __align__(16) float g_dirB[4 * NPLANE];
__device__ __align__(16) float g_s1[NPLANE];

__device__ __forceinline__ void cpa16(unsigned int s, const float* g)
{
    asm volatile("cp.async.cg.shared.global [%0], [%1], 16;\n"
                 :: "r"(s), "l"(g) : "memory");
}

__device__ __forceinline__ float4 norm4(float a1, float a2, float a3, float xv)
{
    float inv = __fdividef(1.0f, fmaxf(fabsf(a1) + fabsf(a2) + fabsf(a3), 1.0f));
    return make_float4(a1 * inv, a2 * inv, a3 * inv,
                       (1.0f - (a1 + a2 + a3) * inv) * xv);
}

// One recurrence step for 8 register-resident elements + shfl halos.
__device__ __forceinline__ void scan_step(const float4* q, float* h, int lane)
{
    float hu = __shfl_up_sync(FULLMASK, h[7], 1);
    float hd = __shfl_down_sync(FULLMASK, h[0], 1);
    if (lane == 0)  hu = 0.f;
    if (lane >= 27) hd = 0.f;
    float nh[8];
    nh[0] = fmaf(q[0].x, hu, fmaf(q[0].y, h[0], fmaf(q[0].z, h[1], q[0].w)));
#pragma unroll
    for (int i = 1; i < 7; i++)
        nh[i] = fmaf(q[i].x, h[i-1], fmaf(q[i].y, h[i], fmaf(q[i].z, h[i+1], q[i].w)));
    nh[7] = fmaf(q[7].x, h[6], fmaf(q[7].y, h[7], fmaf(q[7].z, hd, q[7].w)));
#pragma unroll
    for (int i = 0; i < 8; i++) h[i] = nh[i];
}

// ---------------------------------------------------------------------------
// conv1: y [4,2,224,224] -> g_y32 [4,32,224,224], 3x3 same
// ---------------------------------------------------------------------------
__global__ void __launch_bounds__(224) conv1_kernel(
    const float* __restrict__ y, const float* __restrict__ w3)
{
    int b = blockIdx.x / HH;
    int h = blockIdx.x % HH;
    int tid = threadIdx.x;

    __shared__ float si[2][3][WW + 2];
    __shared__ float sw[32 * 2 * 9];

    for (int i = tid; i < 576; i += 224) sw[i] = w3[i];

    #pragma unroll
    for (int ic = 0; ic < 2; ic++)
        #pragma unroll
        for (int r = 0; r < 3; r++) {
            int hh = h + r - 1;
            float v = (hh >= 0 && hh < HH)
                        ? y[((size_t)(b * 2 + ic) * HH + hh) * WW + tid] : 0.f;
            si[ic][r][tid + 1] = v;
            if (tid < 2) si[ic][r][tid * (WW + 1)] = 0.f;
        }
    __syncthreads();

    float v[18];
    #pragma unroll
    for (int ic = 0; ic < 2; ic++)
        #pragma unroll
        for (int r = 0; r < 3; r++)
            #pragma unroll
            for (int dx = 0; dx < 3; dx++)
                v[ic * 9 + r * 3 + dx] = si[ic][r][tid + dx];

    for (int oc = 0; oc < 32; oc++) {
        float acc = 0.f;
        #pragma unroll
        for (int k = 0; k < 18; k++) acc = fmaf(v[k], sw[oc * 18 + k], acc);
        g_y32[((size_t)(b * 32 + oc) * HH + h) * WW + tid] = acc;
    }
}

// ---------------------------------------------------------------------------
// Propagation: ONE WARP PER CTA, no CTA barriers, static smem (<48KB).
// 28 lanes x 8 elements in registers; halo exchange via shfl; gates streamed
// via cp.async 16B chunks, double-buffered 4-step tiles.
// dir map: 0=lr(hor,fwd) 1=rl(vert,rev) 2=du(vert,fwd) 3=ud(hor,rev)
// ---------------------------------------------------------------------------
__global__ void __launch_bounds__(32) prop_kernel(
    const float* __restrict__ gates, int pass)
{
    // 45,824 B static shared (one warp's working set)
    __shared__ __align__(16) float swarp[11456];

    int lane = threadIdx.x & 31;
    int d  = blockIdx.x >> 7;           // 0..3
    int bc = blockIdx.x & 127;
    int b  = bc >> 5;
    int c  = bc & 31;
    bool hor = (d == 0 || d == 3);
    bool rev = (d == 1 || d == 3);

    const float* xin = pass ? g_s1 : g_y32;
    const float* gp[4];
    gp[0] = xin + (size_t)bc * HW;
    gp[1] = gates + ((size_t)b * GCH + d * 96 + c) * HW;
    gp[2] = gp[1] + (size_t)32 * HW;
    gp[3] = gp[1] + (size_t)64 * HW;
    float* op = (pass ? g_dirB : g_dirA) + (size_t)(d * 128 + bc) * HW;

    float*  rawf  = swarp;
    float4* nrm4p = (float4*)(swarp + 7168);   // byte offset 28672

    // Tile prefetch via cp.async (16B chunks). 28 instrs per tile.
    auto prefetch = [&](int tb, int buf) {
        int t0 = tb * 4;
        if (hor) {
            // chunk = 4 consecutive steps of one row el: raw[a][el][0..3]
            int tg0 = rev ? (220 - t0) : t0;
#pragma unroll
            for (int i = 0; i < 7; i++) {
                int el = i * 32 + lane;             // 0..223
                int fidx = buf * 3584 + el * 4;
#pragma unroll
                for (int a = 0; a < 4; a++) {
                    unsigned int dst = (unsigned int)
                        __cvta_generic_to_shared(rawf + fidx + a * 896);
                    cpa16(dst, gp[a] + (size_t)el * WW + tg0);
                }
            }
        } else {
            // chunk = 4 consecutive elements at step j: raw[a][j][e]
            // padded: element e stored at e + (e>>3)*4 (row 336 floats)
#pragma unroll
            for (int i = 0; i < 7; i++) {
                int k  = i * 32 + lane;             // 0..223
                int j  = k / 56;
                int e0 = (k % 56) * 4;
                int tg = rev ? (223 - t0 - j) : (t0 + j);
                int fidx = buf * 5376 + j * 336 + e0 + ((e0 >> 3) << 2);
#pragma unroll
                for (int a = 0; a < 4; a++) {
                    unsigned int dst = (unsigned int)
                        __cvta_generic_to_shared(rawf + fidx + a * 1344);
                    cpa16(dst, gp[a] + (size_t)tg * WW + e0);
                }
            }
        }
        asm volatile("cp.async.commit_group;" ::: "memory");
    };

    prefetch(0, 0);

    float h[8];
#pragma unroll
    for (int i = 0; i < 8; i++) h[i] = 0.f;
    int el0 = lane * 8;

    for (int tb = 0; tb < 56; tb++) {
        int buf = tb & 1;
        int t0 = tb * 4;
        if (tb + 1 < 56) {
            prefetch(tb + 1, buf ^ 1);
            asm volatile("cp.async.wait_group 1;" ::: "memory");
        } else {
            asm volatile("cp.async.wait_group 0;" ::: "memory");
        }
        __syncwarp();

        if (hor) {
            // ---- normalize + transpose raw -> nrm[j][el + (el>>3)] ----
#pragma unroll
            for (int i = 0; i < 7; i++) {
                int el = i * 32 + lane;
                const float* base = rawf + buf * 3584 + el * 4;
                float4 xv = *(const float4*)(base);
                float4 a1 = *(const float4*)(base + 896);
                float4 a2 = *(const float4*)(base + 1792);
                float4 a3 = *(const float4*)(base + 2688);
                float vx[4] = {xv.x, xv.y, xv.z, xv.w};
                float v1[4] = {a1.x, a1.y, a1.z, a1.w};
                float v2[4] = {a2.x, a2.y, a2.z, a2.w};
                float v3[4] = {a3.x, a3.y, a3.z, a3.w};
#pragma unroll
                for (int j = 0; j < 4; j++) {
                    int jj = rev ? 3 - j : j;
                    nrm4p[j * 260 + el + (el >> 3)] =
                        norm4(v1[jj], v2[jj], v3[jj], vx[jj]);
                }
            }
            __syncwarp();

            float o[4][8];
#pragma unroll
            for (int j = 0; j < 4; j++) {
                float4 q[8];
                const float4* nb = nrm4p + j * 260 + lane * 9;
#pragma unroll
                for (int i = 0; i < 8; i++) q[i] = nb[i];
                scan_step(q, h, lane);
#pragma unroll
                for (int i = 0; i < 8; i++) o[j][i] = h[i];
            }
            if (lane < 28) {
                int tg0 = rev ? (220 - t0) : t0;
#pragma unroll
                for (int i = 0; i < 8; i++) {
                    float4 v = rev
                        ? make_float4(o[3][i], o[2][i], o[1][i], o[0][i])
                        : make_float4(o[0][i], o[1][i], o[2][i], o[3][i]);
                    *(float4*)(op + (size_t)(el0 + i) * WW + tg0) = v;
                }
            }
            __syncwarp();
        } else {
#pragma unroll
            for (int j = 0; j < 4; j++) {
                const float* base = rawf + buf * 5376 + j * 336 + lane * 12;
                float4 x0  = *(const float4*)(base);
                float4 x1  = *(const float4*)(base + 4);
                float4 g10 = *(const float4*)(base + 1344);
                float4 g11 = *(const float4*)(base + 1348);
                float4 g20 = *(const float4*)(base + 2688);
                float4 g21 = *(const float4*)(base + 2692);
                float4 g30 = *(const float4*)(base + 4032);
                float4 g31 = *(const float4*)(base + 4036);
                float4 q[8];
                q[0] = norm4(g10.x, g20.x, g30.x, x0.x);
                q[1] = norm4(g10.y, g20.y, g30.y, x0.y);
                q[2] = norm4(g10.z, g20.z, g30.z, x0.z);
                q[3] = norm4(g10.w, g20.w, g30.w, x0.w);
                q[4] = norm4(g11.x, g21.x, g31.x, x1.x);
                q[5] = norm4(g11.y, g21.y, g31.y, x1.y);
                q[6] = norm4(g11.z, g21.z, g31.z, x1.z);
                q[7] = norm4(g11.w, g21.w, g31.w, x1.w);
                scan_step(q, h, lane);
                if (lane < 28) {
                    int tg = rev ? (223 - t0 - j) : (t0 + j);
                    *(float4*)(op + (size_t)tg * WW + el0) =
                        make_float4(h[0], h[1], h[2], h[3]);
                    *(float4*)(op + (size_t)tg * WW + el0 + 4) =
                        make_float4(h[4], h[5], h[6], h[7]);
                }
            }
            __syncwarp();
        }
    }
}

// ---------------------------------------------------------------------------
// max over 4 pass-1 direction buffers -> g_s1
// ---------------------------------------------------------------------------
__global__ void max_kernel()
{
    int i = blockIdx.x * blockDim.x + threadIdx.x;
    if (i >= N4) return;
    const float4* d0 = (const float4*)g_dirA;
    float4 a = d0[i];
    float4 b = d0[i + N4];
    float4 c = d0[i + 2 * N4];
    float4 e = d0[i + 3 * N4];
    float4 r;
    r.x = fmaxf(fmaxf(a.x, b.x), fmaxf(c.x, e.x));
    r.y = fmaxf(fmaxf(a.y, b.y), fmaxf(c.y, e.y));
    r.z = fmaxf(fmaxf(a.z, b.z), fmaxf(c.z, e.z));
    r.w = fmaxf(fmaxf(a.w, b.w), fmaxf(c.w, e.w));
    ((float4*)g_s1)[i] = r;
}

// ---------------------------------------------------------------------------
// conv2 (32->2, 3x3 same) fused with max over 4 pass-2 dirs + log_softmax
// ---------------------------------------------------------------------------
__global__ void __launch_bounds__(224) conv2_ls_kernel(
    const float* __restrict__ w4, float* __restrict__ out)
{
    int b = blockIdx.x / HH;
    int h = blockIdx.x % HH;
    int tid = threadIdx.x;

    __shared__ float si[16][3][WW + 2];
    __shared__ float sw[2 * 32 * 9];

    for (int i = tid; i < 576; i += 224) sw[i] = w4[i];

    float acc0 = 0.f, acc1 = 0.f;

    for (int chunk = 0; chunk < 2; chunk++) {
        __syncthreads();
        for (int icl = 0; icl < 16; icl++) {
            int ic = chunk * 16 + icl;
            #pragma unroll
            for (int r = 0; r < 3; r++) {
                int hh = h + r - 1;
                float v = 0.f;
                if (hh >= 0 && hh < HH) {
                    size_t base = ((size_t)(b * 32 + ic) * HH + hh) * WW + tid;
                    float v0 = g_dirB[base];
                    float v1 = g_dirB[base + 1 * (size_t)NPLANE];
                    float v2 = g_dirB[base + 2 * (size_t)NPLANE];
                    float v3 = g_dirB[base + 3 * (size_t)NPLANE];
                    v = fmaxf(fmaxf(v0, v1), fmaxf(v2, v3));
                }
                si[icl][r][tid + 1] = v;
                if (tid < 2) si[icl][r][tid * (WW + 1)] = 0.f;
            }
        }
        __syncthreads();
        for (int icl = 0; icl < 16; icl++) {
            int ic = chunk * 16 + icl;
            #pragma unroll
            for (int r = 0; r < 3; r++)
                #pragma unroll
                for (int dx = 0; dx < 3; dx++) {
                    float v = si[icl][r][tid + dx];
                    int k = ic * 9 + r * 3 + dx;
                    acc0 = fmaf(v, sw[k], acc0);
                    acc1 = fmaf(v, sw[288 + k], acc1);
                }
        }
    }

    float m  = fmaxf(acc0, acc1);
    float e0 = __expf(acc0 - m), e1 = __expf(acc1 - m);
    float lse = m + __logf(e0 + e1);
    size_t o = ((size_t)b * 2 * HH + h) * WW + tid;
    out[o]      = acc0 - lse;
    out[o + HW] = acc1 - lse;
}

// ---------------------------------------------------------------------------
extern "C" void kernel_launch(void* const* d_in, const int* in_sizes, int n_in,
                              void* d_out, int out_size)
{
    const float* gates = (const float*)d_in[0];  // [4,384,224,224]
    const float* y     = (const float*)d_in[1];  // [4,2,224,224]
    const float* w3    = (const float*)d_in[2];  // [32,2,3,3]
    const float* w4    = (const float*)d_in[3];  // [2,32,3,3]
    float* out = (float*)d_out;                  // [4,2,224,224]

    (void)in_sizes; (void)n_in; (void)out_size;

    conv1_kernel<<<BB * HH, 224>>>(y, w3);
    prop_kernel<<<512, 32>>>(gates, 0);      // -> g_dirA
    max_kernel<<<(N4 + 255) / 256, 256>>>(); // g_dirA -> g_s1
    prop_kernel<<<512, 32>>>(gates, 1);      // x=g_s1 -> g_dirB
    conv2_ls_kernel<<<BB * HH, 224>>>(w4, out);
}